// round 1
// baseline (speedup 1.0000x reference)
#include <cuda_runtime.h>
#include <math.h>

#define BB 32
#define TT 8
#define NN 512
#define FF 4
#define HH 64
#define COO 12
#define ROWS (BB*TT*NN)     /* 131072 rows over (b,t,n) */
#define BTN  (BB*TT)        /* 256 (b,t) pairs */

// ---------------- scratch (static device globals; no allocation) ----------------
__device__ float        d_Wx[ROWS*HH];            // 33.5 MB  [row][h]
__device__ float        d_asrc[ROWS];
__device__ float        d_adst[ROWS];
__device__ unsigned int d_maskbits[ROWS*(NN/32)]; // 8.4 MB   [bt][i][word]
__device__ float        d_gates[ROWS*12];         // 6.3 MB   [row][12]
__device__ float        d_g[BB*TT*NN*FF];         // 2 MB     [b][t][n][f]

// ================= K1: Wx = x @ gat_W ; a_src/a_dst dots (warp per row) ==========
__global__ void k_wx(const float* __restrict__ x, const float* __restrict__ gat_W,
                     const float* __restrict__ att_src, const float* __restrict__ att_dst)
{
    int gw   = (blockIdx.x * blockDim.x + threadIdx.x) >> 5;
    int lane = threadIdx.x & 31;
    if (gw >= ROWS) return;
    float x0 = __ldg(&x[gw*4+0]);
    float x1 = __ldg(&x[gw*4+1]);
    float x2 = __ldg(&x[gw*4+2]);
    float x3 = __ldg(&x[gw*4+3]);
    // gat_W layout [f*64 + h]
    float w0 = x0*__ldg(&gat_W[      lane]) + x1*__ldg(&gat_W[ 64+lane])
             + x2*__ldg(&gat_W[128+  lane]) + x3*__ldg(&gat_W[192+lane]);
    float w1 = x0*__ldg(&gat_W[ 32 + lane]) + x1*__ldg(&gat_W[ 96+lane])
             + x2*__ldg(&gat_W[160 + lane]) + x3*__ldg(&gat_W[224+lane]);
    d_Wx[(size_t)gw*64 +      lane] = w0;
    d_Wx[(size_t)gw*64 + 32 + lane] = w1;
    float s = w0*__ldg(&att_src[lane]) + w1*__ldg(&att_src[32+lane]);
    float d = w0*__ldg(&att_dst[lane]) + w1*__ldg(&att_dst[32+lane]);
    #pragma unroll
    for (int o = 16; o > 0; o >>= 1) {
        s += __shfl_xor_sync(0xffffffffu, s, o);
        d += __shfl_xor_sync(0xffffffffu, d, o);
    }
    if (lane == 0) { d_asrc[gw] = s; d_adst[gw] = d; }
}

// ====== K2: transpose adjacency + bit-pack mask: bit(j) of word[bt][i][tj] =======
// mask[i][j] = (adj[bt][j][i] != 0) || (i == j)
__global__ void k_mask(const float* __restrict__ adj)
{
    __shared__ unsigned char s[32][33];
    int ti = blockIdx.x, tj = blockIdx.y, bt = blockIdx.z;
    int tx = threadIdx.x, ty = threadIdx.y;
    #pragma unroll
    for (int r = 0; r < 4; r++) {
        int jl = ty + r*8;
        int j  = tj*32 + jl;
        int i  = ti*32 + tx;
        float v = adj[((size_t)bt*NN + j)*NN + i];     // coalesced over i
        s[jl][tx] = (v != 0.0f) ? 1 : 0;
    }
    __syncthreads();
    int warp = ty, lane = tx;
    #pragma unroll
    for (int r = 0; r < 4; r++) {
        int il = warp*4 + r;
        int gi = ti*32 + il;
        int gj = tj*32 + lane;
        bool pred = (s[lane][il] != 0) || (gi == gj);
        unsigned int word = __ballot_sync(0xffffffffu, pred);
        if (lane == 0)
            d_maskbits[((size_t)bt*NN + gi)*16 + tj] = word;
    }
}

// ===== K3: fused GAT softmax-aggregation + bias + GRU input gates ================
// CTA = (bt, half): 256 queries. 8 warps x 32 queries, processed in groups of 8.
__global__ void __launch_bounds__(256, 1)
k_attn(const float* __restrict__ gat_bias,
       const float* __restrict__ W_ih, const float* __restrict__ b_ih)
{
    extern __shared__ float smem[];
    float* sWx   = smem;                 // 512*64 = 32768 floats
    float* sAsrc = sWx + 32768;          // 512
    float* sWih  = sAsrc + 512;          // 768  (12 x 64)
    float* pt    = sWih + 768;           // 8 warps * 8 q * 36

    int bt   = blockIdx.x >> 1;
    int half = blockIdx.x & 1;
    int tid  = threadIdx.x;
    int w    = tid >> 5;
    int lane = tid & 31;

    // stage Wx tile, a_src, W_ih to smem
    {
        const float4* gWx = (const float4*)(d_Wx + (size_t)bt*NN*HH);
        float4* sWx4 = (float4*)sWx;
        for (int i = tid; i < 8192; i += 256) sWx4[i] = gWx[i];
        for (int i = tid; i < 512;  i += 256) sAsrc[i] = d_asrc[bt*NN + i];
        for (int i = tid; i < 768;  i += 256) sWih[i]  = __ldg(&W_ih[i]);
    }
    __syncthreads();

    // per-warp global max of a_src (for safe softmax shift)
    float sx = -1e30f;
    #pragma unroll
    for (int t = 0; t < 16; t++) sx = fmaxf(sx, sAsrc[t*32 + lane]);
    #pragma unroll
    for (int o = 16; o > 0; o >>= 1) sx = fmaxf(sx, __shfl_xor_sync(0xffffffffu, sx, o));

    float gb0 = __ldg(&gat_bias[lane]);
    float gb1 = __ldg(&gat_bias[32 + lane]);
    float* ptw = pt + w * (8*36);
    const unsigned int* mb = d_maskbits + (size_t)bt*NN*16;

    for (int g = 0; g < 4; g++) {
        int i0 = half*256 + w*32 + g*8;
        float dq[8], mq[8], lpart[8], acc0[8], acc1[8];
        #pragma unroll
        for (int q = 0; q < 8; q++) {
            dq[q] = __ldg(&d_adst[bt*NN + i0 + q]);
            mq[q] = fmaxf(0.0f, dq[q] + sx);       // >= max over j of lrelu(dq+sj)
            lpart[q] = 0.0f; acc0[q] = 0.0f; acc1[q] = 0.0f;
        }
        for (int tile = 0; tile < 16; tile++) {
            float sj = sAsrc[tile*32 + lane];
            // ---- phase A: probabilities for 8 queries (lane == j within tile) ----
            #pragma unroll
            for (int q = 0; q < 8; q++) {
                unsigned int wq = __ldg(&mb[(i0 + q)*16 + tile]);
                float e = dq[q] + sj;
                e = e > 0.0f ? e : 0.2f*e;          // leaky_relu(0.2)
                float p = ((wq >> lane) & 1u) ? __expf(e - mq[q]) : 0.0f;
                ptw[q*36 + lane] = p;
                lpart[q] += p;
            }
            __syncwarp();
            // ---- phase B: rank-update accumulation (lane == h, h+32) ----
            #pragma unroll
            for (int v = 0; v < 8; v++) {
                float4 p4[8];
                #pragma unroll
                for (int q = 0; q < 8; q++)
                    p4[q] = *(const float4*)&ptw[q*36 + v*4];
                #pragma unroll
                for (int dj = 0; dj < 4; dj++) {
                    int j = tile*32 + v*4 + dj;
                    float wx0 = sWx[j*64 + lane];
                    float wx1 = sWx[j*64 + 32 + lane];
                    #pragma unroll
                    for (int q = 0; q < 8; q++) {
                        float p = (dj == 0) ? p4[q].x : (dj == 1) ? p4[q].y
                                : (dj == 2) ? p4[q].z : p4[q].w;
                        acc0[q] = fmaf(p, wx0, acc0[q]);
                        acc1[q] = fmaf(p, wx1, acc1[q]);
                    }
                }
            }
            __syncwarp();
        }
        // ---- epilogue: normalize, +bias, fused 64->12 gate projection ----
        #pragma unroll
        for (int q = 0; q < 8; q++) {
            float l = lpart[q];
            #pragma unroll
            for (int o = 16; o > 0; o >>= 1) l += __shfl_xor_sync(0xffffffffu, l, o);
            float inv = 1.0f / l;
            float o0 = acc0[q]*inv + gb0;
            float o1 = acc1[q]*inv + gb1;
            int row = bt*NN + i0 + q;
            #pragma unroll
            for (int k = 0; k < 12; k++) {
                float t2 = sWih[k*64 + lane]*o0 + sWih[k*64 + 32 + lane]*o1;
                #pragma unroll
                for (int o = 16; o > 0; o >>= 1) t2 += __shfl_xor_sync(0xffffffffu, t2, o);
                if (lane == 0)
                    d_gates[(size_t)row*12 + k] = t2 + __ldg(&b_ih[k]);
            }
        }
    }
}

// ===================== K4: GRU recurrence (thread per sequence) ==================
__device__ __forceinline__ float sigm(float v) { return 1.0f / (1.0f + __expf(-v)); }

__global__ void k_gru(const float* __restrict__ W_hh, const float* __restrict__ b_hh)
{
    __shared__ float sWhh[48], sbhh[12];
    int tid = threadIdx.x;
    if (tid < 48) sWhh[tid] = W_hh[tid];
    if (tid < 12) sbhh[tid] = b_hh[tid];
    __syncthreads();
    int q = blockIdx.x * blockDim.x + tid;
    if (q >= BB*NN) return;
    int b = q >> 9, n = q & 511;
    float h0 = 0.f, h1 = 0.f, h2 = 0.f, h3 = 0.f;
    #pragma unroll
    for (int s = 0; s < TT; s++) {
        const float* gx = d_gates + (size_t)(q*8 + s)*12;
        float4 g0 = *(const float4*)(gx + 0);
        float4 g1 = *(const float4*)(gx + 4);
        float4 g2 = *(const float4*)(gx + 8);
        float gh[12];
        #pragma unroll
        for (int k = 0; k < 12; k++)
            gh[k] = sbhh[k] + sWhh[k*4+0]*h0 + sWhh[k*4+1]*h1
                            + sWhh[k*4+2]*h2 + sWhh[k*4+3]*h3;
        float r0 = sigm(g0.x + gh[0]), r1 = sigm(g0.y + gh[1]);
        float r2 = sigm(g0.z + gh[2]), r3 = sigm(g0.w + gh[3]);
        float z0 = sigm(g1.x + gh[4]), z1 = sigm(g1.y + gh[5]);
        float z2 = sigm(g1.z + gh[6]), z3 = sigm(g1.w + gh[7]);
        float c0 = tanhf(g2.x + r0*gh[8]),  c1 = tanhf(g2.y + r1*gh[9]);
        float c2 = tanhf(g2.z + r2*gh[10]), c3 = tanhf(g2.w + r3*gh[11]);
        h0 = (1.0f - z0)*c0 + z0*h0;
        h1 = (1.0f - z1)*c1 + z1*h1;
        h2 = (1.0f - z2)*c2 + z2*h2;
        h3 = (1.0f - z3)*c3 + z3*h3;
        float4 ov = make_float4(h0, h1, h2, h3);
        *(float4*)&d_g[(((size_t)b*TT + s)*NN + n)*4] = ov;   // g[b, t=s, n, :]
    }
}

// ============== K5: Conv2d(8->12, 3x3, SAME) fused with Linear(4->2) =============
__global__ void k_conv(const float* __restrict__ conv_W, const float* __restrict__ conv_b,
                       const float* __restrict__ out_W,  const float* __restrict__ out_b,
                       float* __restrict__ out)
{
    __shared__ float sW[864];     // [co][ci][kh][kw]
    __shared__ float sOW[8], sOB[2], sCB[12];
    int tid = threadIdx.x;
    for (int i = tid; i < 864; i += 256) sW[i] = conv_W[i];
    if (tid < 8)  sOW[tid] = out_W[tid];
    if (tid < 2)  sOB[tid] = out_b[tid];
    if (tid < 12) sCB[tid] = conv_b[tid];
    __syncthreads();

    int idx = blockIdx.x * 256 + tid;          // over (b, co, n): 32*12*512
    int n  = idx & 511;
    int co = (idx >> 9) % 12;
    int b  = idx / (512*12);

    float y0, y1, y2, y3;
    y0 = y1 = y2 = y3 = sCB[co];
    #pragma unroll
    for (int ci = 0; ci < 8; ci++) {
        #pragma unroll
        for (int kh = 0; kh < 3; kh++) {
            int nn = n + kh - 1;
            float4 v = make_float4(0.f, 0.f, 0.f, 0.f);
            if (nn >= 0 && nn < 512)
                v = *(const float4*)&d_g[(((size_t)b*8 + ci)*512 + nn)*4];
            const float* wr = &sW[(co*8 + ci)*9 + kh*3];
            float w0 = wr[0], w1 = wr[1], w2 = wr[2];
            y0 += v.x*w1 + v.y*w2;
            y1 += v.x*w0 + v.y*w1 + v.z*w2;
            y2 += v.y*w0 + v.z*w1 + v.w*w2;
            y3 += v.z*w0 + v.w*w1;
        }
    }
    float o0 = sOB[0] + y0*sOW[0] + y1*sOW[1] + y2*sOW[2] + y3*sOW[3];
    float o1 = sOB[1] + y0*sOW[4] + y1*sOW[5] + y2*sOW[6] + y3*sOW[7];
    float2 ov = make_float2(o0, o1);
    *(float2*)&out[(size_t)idx*2] = ov;
}

// ================================ launch =========================================
extern "C" void kernel_launch(void* const* d_in, const int* in_sizes, int n_in,
                              void* d_out, int out_size)
{
    const float* x        = (const float*)d_in[0];
    const float* adj      = (const float*)d_in[1];
    const float* gat_W    = (const float*)d_in[2];
    const float* att_src  = (const float*)d_in[3];
    const float* att_dst  = (const float*)d_in[4];
    const float* gat_bias = (const float*)d_in[5];
    const float* W_ih     = (const float*)d_in[6];
    const float* W_hh     = (const float*)d_in[7];
    const float* b_ih     = (const float*)d_in[8];
    const float* b_hh     = (const float*)d_in[9];
    const float* conv_W   = (const float*)d_in[10];
    const float* conv_b   = (const float*)d_in[11];
    const float* out_W    = (const float*)d_in[12];
    const float* out_b    = (const float*)d_in[13];
    float* out = (float*)d_out;

    const int attn_smem = (32768 + 512 + 768 + 8*8*36) * 4;   // 145408 bytes
    cudaFuncSetAttribute(k_attn, cudaFuncAttributeMaxDynamicSharedMemorySize, attn_smem);

    k_wx<<<ROWS/8, 256>>>(x, gat_W, att_src, att_dst);

    dim3 gm(16, 16, BTN), bm(32, 8);
    k_mask<<<gm, bm>>>(adj);

    k_attn<<<512, 256, attn_smem>>>(gat_bias, W_ih, b_ih);

    k_gru<<<(BB*NN)/256, 256>>>(W_hh, b_hh);

    k_conv<<<768, 256>>>(conv_W, conv_b, out_W, out_b, out);
}

// round 3
// speedup vs baseline: 1.9244x; 1.9244x over previous
#include <cuda_runtime.h>
#include <cuda_fp16.h>
#include <math.h>
#include <cstdint>

#define BB 32
#define TT 8
#define NN 512
#define FF 4
#define HH 64
#define COO 12
#define ROWS (BB*TT*NN)
#define BTN  (BB*TT)

// ---------------- scratch (static device globals; no allocation) ----------------
__device__ __half       d_WxT[(size_t)BTN*HH*NN];   // 16.8 MB  [bt][h][j] fp16
__device__ float        d_asrc[ROWS];
__device__ float        d_adst[ROWS];
__device__ unsigned int d_maskbits[ROWS*(NN/32)];   // 8.4 MB [bt][i][word]
__device__ float        d_gates[(size_t)ROWS*12];   // 6.3 MB
__device__ float        d_g[BB*TT*NN*FF];           // 2 MB

// ============ K1: WxT fp16 + a_src/a_dst (per-bt block) ==========================
__global__ void k_proj(const float* __restrict__ x, const float* __restrict__ gat_W,
                       const float* __restrict__ att_src, const float* __restrict__ att_dst)
{
    __shared__ float4 sx4[NN];
    __shared__ float  sW[256];
    __shared__ float  su[4], sv[4];
    int bt = blockIdx.x, tid = threadIdx.x;
    int w = tid >> 5, lane = tid & 31;

    const float4* gx = (const float4*)(x + (size_t)bt*NN*FF);
    sx4[tid] = gx[tid];
    sx4[tid + 256] = gx[tid + 256];
    if (tid < 256) sW[tid] = gat_W[tid];
    __syncthreads();

    if (w == 0) {
        float as0 = __ldg(&att_src[lane]), as1 = __ldg(&att_src[32 + lane]);
        float ad0 = __ldg(&att_dst[lane]), ad1 = __ldg(&att_dst[32 + lane]);
        #pragma unroll
        for (int f = 0; f < 4; f++) {
            float uu = sW[f*64 + lane]*as0 + sW[f*64 + 32 + lane]*as1;
            float vv = sW[f*64 + lane]*ad0 + sW[f*64 + 32 + lane]*ad1;
            #pragma unroll
            for (int o = 16; o > 0; o >>= 1) {
                uu += __shfl_xor_sync(0xffffffffu, uu, o);
                vv += __shfl_xor_sync(0xffffffffu, vv, o);
            }
            if (lane == 0) { su[f] = uu; sv[f] = vv; }
        }
    }
    __syncthreads();

    __half2* wt = (__half2*)(d_WxT + (size_t)bt*HH*NN);
    for (int h = w; h < 64; h += 8) {
        float w0 = sW[h], w1 = sW[64 + h], w2 = sW[128 + h], w3 = sW[192 + h];
        #pragma unroll
        for (int jc = 0; jc < 8; jc++) {
            int j = jc*64 + lane*2;
            float4 a = sx4[j], b = sx4[j + 1];
            float wx0 = a.x*w0 + a.y*w1 + a.z*w2 + a.w*w3;
            float wx1 = b.x*w0 + b.y*w1 + b.z*w2 + b.w*w3;
            wt[(h*NN + j) >> 1] = __floats2half2_rn(wx0, wx1);
        }
    }
    #pragma unroll
    for (int r = 0; r < 2; r++) {
        int j = tid + r*256;
        float4 a = sx4[j];
        d_asrc[bt*NN + j] = a.x*su[0] + a.y*su[1] + a.z*su[2] + a.w*su[3];
        d_adst[bt*NN + j] = a.x*sv[0] + a.y*sv[1] + a.z*sv[2] + a.w*sv[3];
    }
}

// ====== K2: transpose adjacency + bit-pack mask ==================================
__global__ void k_mask(const float* __restrict__ adj)
{
    __shared__ unsigned char s[32][33];
    int ti = blockIdx.x, tj = blockIdx.y, bt = blockIdx.z;
    int tx = threadIdx.x, ty = threadIdx.y;
    #pragma unroll
    for (int r = 0; r < 4; r++) {
        int jl = ty + r*8;
        int j  = tj*32 + jl;
        int i  = ti*32 + tx;
        float v = adj[((size_t)bt*NN + j)*NN + i];
        s[jl][tx] = (v != 0.0f) ? 1 : 0;
    }
    __syncthreads();
    #pragma unroll
    for (int r = 0; r < 4; r++) {
        int il = ty*4 + r;
        int gi = ti*32 + il;
        int gj = tj*32 + tx;
        bool pred = (s[tx][il] != 0) || (gi == gj);
        unsigned int word = __ballot_sync(0xffffffffu, pred);
        if (tx == 0)
            d_maskbits[((size_t)bt*NN + gi)*16 + tj] = word;
    }
}

// ===== K3: HMMA fused attention: softmax-P -> mma.16816 -> normalize -> gates ====
// CTA = (bt, mtile of 128 queries). P[128,512] fp16, WxT[64,512] fp16, padded rows.
#define PSTRIDE 1040              /* (512+8) halves * 2B; 1040 % 128 == 16 */
#define SME_P       0             /* 128*1040 = 133120 */
#define SME_B       133120        /* 64*1040  = 66560  */
#define SME_ASRC    199680        /* 2048 */
#define SME_WIH     201728        /* 3072 */
#define SME_BIAS    204800        /* 256  */
#define SME_BIH     205056        /* 64   */
#define SME_L       205120        /* 512  */
#define SME_TOTAL   205632
#define DSTRIDE 66                /* floats; D reuses SME_P region */

__device__ __forceinline__ void mma16816(float* d, const uint32_t* a, const uint32_t* b)
{
    asm volatile("mma.sync.aligned.m16n8k16.row.col.f32.f16.f16.f32 "
        "{%0,%1,%2,%3}, {%4,%5,%6,%7}, {%8,%9}, {%0,%1,%2,%3};"
        : "+f"(d[0]), "+f"(d[1]), "+f"(d[2]), "+f"(d[3])
        : "r"(a[0]), "r"(a[1]), "r"(a[2]), "r"(a[3]), "r"(b[0]), "r"(b[1]));
}

__global__ void __launch_bounds__(256, 1)
k_attn(const float* __restrict__ gat_bias,
       const float* __restrict__ W_ih, const float* __restrict__ b_ih)
{
    extern __shared__ char smem[];
    float* sAsrc = (float*)(smem + SME_ASRC);
    float* sWih  = (float*)(smem + SME_WIH);
    float* sBias = (float*)(smem + SME_BIAS);
    float* sBih  = (float*)(smem + SME_BIH);
    float* sL    = (float*)(smem + SME_L);

    int bt    = blockIdx.x >> 2;
    int mtile = blockIdx.x & 3;
    int tid   = threadIdx.x;
    int w     = tid >> 5, lane = tid & 31;

    // ---- stage B tile: WxT[64][512] -> padded smem rows ----
    {
        const uint4* gB = (const uint4*)(d_WxT + (size_t)bt*HH*NN);
        #pragma unroll
        for (int t = tid; t < 4096; t += 256) {
            int n = t >> 6, c = t & 63;
            *(uint4*)(smem + SME_B + n*PSTRIDE + c*16) = gB[t];
        }
    }
    for (int i = tid; i < 512; i += 256) sAsrc[i] = d_asrc[bt*NN + i];
    for (int i = tid; i < 768; i += 256) sWih[i]  = __ldg(&W_ih[i]);
    if (tid < 64) sBias[tid] = __ldg(&gat_bias[tid]);
    if (tid < 12) sBih[tid]  = __ldg(&b_ih[tid]);
    __syncthreads();

    // warp-uniform max of a_src
    float sx = -1e30f;
    #pragma unroll
    for (int t = 0; t < 16; t++) sx = fmaxf(sx, sAsrc[t*32 + lane]);
    #pragma unroll
    for (int o = 16; o > 0; o >>= 1) sx = fmaxf(sx, __shfl_xor_sync(0xffffffffu, sx, o));

    // ---- phase A: P numerators (fp16) + row sums of rounded values ----
    const unsigned int* mb = d_maskbits + (size_t)bt*NN*16;
    #pragma unroll 1
    for (int qi = 0; qi < 16; qi++) {
        int q = w*16 + qi;
        int i = mtile*128 + q;
        float dq = __ldg(&d_adst[bt*NN + i]);
        float mq = fmaxf(0.0f, dq + sx);
        float lp = 0.0f;
        #pragma unroll
        for (int jt = 0; jt < 8; jt++) {
            int j = jt*64 + lane*2;
            float2 sj = *(const float2*)&sAsrc[j];
            unsigned int word = __ldg(&mb[(size_t)i*16 + jt*2 + (lane >> 4)]);
            int bit = (lane & 15)*2;
            float t0 = dq + sj.x;
            float t1 = dq + sj.y;
            float e0 = fmaxf(t0, 0.2f*t0) - mq;
            float e1 = fmaxf(t1, 0.2f*t1) - mq;
            float p0 = ((word >> bit) & 1u)     ? __expf(e0) : 0.0f;
            float p1 = ((word >> (bit+1)) & 1u) ? __expf(e1) : 0.0f;
            __half2 h2 = __floats2half2_rn(p0, p1);
            *(__half2*)(smem + SME_P + q*PSTRIDE + j*2) = h2;
            float2 pr = __half22float2(h2);
            lp += pr.x + pr.y;
        }
        #pragma unroll
        for (int o = 16; o > 0; o >>= 1) lp += __shfl_xor_sync(0xffffffffu, lp, o);
        if (lane == 0) sL[q] = lp;
    }
    __syncthreads();

    // ---- GEMM: D[128,64] = P @ WxT^T; warp tile 32x32 (4m x 2n warp grid) ----
    int mg = w & 3, ng = w >> 2;
    int mbase = mg*32, nbase = ng*32;
    int tm = lane >> 2;            // 0..7
    int tk2 = (lane & 3)*4;        // byte offset of k-pair (k*2)

    float acc[2][4][4];
    #pragma unroll
    for (int mf = 0; mf < 2; mf++)
        #pragma unroll
        for (int nf = 0; nf < 4; nf++)
            #pragma unroll
            for (int r = 0; r < 4; r++) acc[mf][nf][r] = 0.0f;

    const char* Pb = smem + SME_P;
    const char* Bb = smem + SME_B;

    #pragma unroll 4
    for (int ks = 0; ks < 32; ks++) {
        int kb = ks*32 + tk2;                  // byte offset of k columns
        uint32_t a[2][4], b[4][2];
        #pragma unroll
        for (int mf = 0; mf < 2; mf++) {
            int r = mbase + mf*16 + tm;
            a[mf][0] = *(const uint32_t*)(Pb + r*PSTRIDE + kb);
            a[mf][1] = *(const uint32_t*)(Pb + (r+8)*PSTRIDE + kb);
            a[mf][2] = *(const uint32_t*)(Pb + r*PSTRIDE + kb + 16);
            a[mf][3] = *(const uint32_t*)(Pb + (r+8)*PSTRIDE + kb + 16);
        }
        #pragma unroll
        for (int nf = 0; nf < 4; nf++) {
            int n = nbase + nf*8 + tm;
            b[nf][0] = *(const uint32_t*)(Bb + n*PSTRIDE + kb);
            b[nf][1] = *(const uint32_t*)(Bb + n*PSTRIDE + kb + 16);
        }
        #pragma unroll
        for (int mf = 0; mf < 2; mf++)
            #pragma unroll
            for (int nf = 0; nf < 4; nf++)
                mma16816(acc[mf][nf], a[mf], b[nf]);
    }
    __syncthreads();   // all warps done reading P before D overwrites it

    // ---- normalize + bias, write D into (reused) P region ----
    float* D = (float*)(smem + SME_P);
    #pragma unroll
    for (int mf = 0; mf < 2; mf++) {
        int r = mbase + mf*16 + tm;
        float inv0 = 1.0f / sL[r];
        float inv8 = 1.0f / sL[r + 8];
        #pragma unroll
        for (int nf = 0; nf < 4; nf++) {
            int n = nbase + nf*8 + (lane & 3)*2;
            float b0 = sBias[n], b1 = sBias[n + 1];
            *(float2*)&D[r*DSTRIDE + n]       = make_float2(acc[mf][nf][0]*inv0 + b0,
                                                            acc[mf][nf][1]*inv0 + b1);
            *(float2*)&D[(r + 8)*DSTRIDE + n] = make_float2(acc[mf][nf][2]*inv8 + b0,
                                                            acc[mf][nf][3]*inv8 + b1);
        }
    }
    __syncthreads();

    // ---- fused 64->12 GRU input-gate projection ----
    if (tid < 128) {
        int q = tid;
        float o[64];
        #pragma unroll
        for (int h = 0; h < 64; h += 2) {
            float2 v = *(const float2*)&D[q*DSTRIDE + h];
            o[h] = v.x; o[h + 1] = v.y;
        }
        float g[12];
        #pragma unroll
        for (int k = 0; k < 12; k++) {
            float accg = sBih[k];
            #pragma unroll
            for (int h = 0; h < 64; h++) accg = fmaf(sWih[k*64 + h], o[h], accg);
            g[k] = accg;
        }
        float* gp = d_gates + ((size_t)bt*NN + mtile*128 + q)*12;
        *(float4*)(gp + 0) = make_float4(g[0], g[1], g[2],  g[3]);
        *(float4*)(gp + 4) = make_float4(g[4], g[5], g[6],  g[7]);
        *(float4*)(gp + 8) = make_float4(g[8], g[9], g[10], g[11]);
    }
}

// ===================== K4: GRU recurrence ========================================
__device__ __forceinline__ float sigm(float v) { return 1.0f / (1.0f + __expf(-v)); }

__global__ void k_gru(const float* __restrict__ W_hh, const float* __restrict__ b_hh)
{
    __shared__ float sWhh[48], sbhh[12];
    int tid = threadIdx.x;
    if (tid < 48) sWhh[tid] = W_hh[tid];
    if (tid < 12) sbhh[tid] = b_hh[tid];
    __syncthreads();
    int q = blockIdx.x * blockDim.x + tid;
    if (q >= BB*NN) return;
    int b = q >> 9, n = q & 511;
    float h0 = 0.f, h1 = 0.f, h2 = 0.f, h3 = 0.f;
    #pragma unroll
    for (int s = 0; s < TT; s++) {
        const float* gx = d_gates + (size_t)(q*8 + s)*12;
        float4 g0 = *(const float4*)(gx + 0);
        float4 g1 = *(const float4*)(gx + 4);
        float4 g2 = *(const float4*)(gx + 8);
        float gh[12];
        #pragma unroll
        for (int k = 0; k < 12; k++)
            gh[k] = sbhh[k] + sWhh[k*4+0]*h0 + sWhh[k*4+1]*h1
                            + sWhh[k*4+2]*h2 + sWhh[k*4+3]*h3;
        float r0 = sigm(g0.x + gh[0]), r1 = sigm(g0.y + gh[1]);
        float r2 = sigm(g0.z + gh[2]), r3 = sigm(g0.w + gh[3]);
        float z0 = sigm(g1.x + gh[4]), z1 = sigm(g1.y + gh[5]);
        float z2 = sigm(g1.z + gh[6]), z3 = sigm(g1.w + gh[7]);
        float c0 = tanhf(g2.x + r0*gh[8]),  c1 = tanhf(g2.y + r1*gh[9]);
        float c2 = tanhf(g2.z + r2*gh[10]), c3 = tanhf(g2.w + r3*gh[11]);
        h0 = (1.0f - z0)*c0 + z0*h0;
        h1 = (1.0f - z1)*c1 + z1*h1;
        h2 = (1.0f - z2)*c2 + z2*h2;
        h3 = (1.0f - z3)*c3 + z3*h3;
        *(float4*)&d_g[(((size_t)b*TT + s)*NN + n)*4] = make_float4(h0, h1, h2, h3);
    }
}

// ============== K5: Conv2d(8->12, 3x3, SAME) + Linear(4->2) ======================
__global__ void k_conv(const float* __restrict__ conv_W, const float* __restrict__ conv_b,
                       const float* __restrict__ out_W,  const float* __restrict__ out_b,
                       float* __restrict__ out)
{
    __shared__ float sW[864];
    __shared__ float sOW[8], sOB[2], sCB[12];
    int tid = threadIdx.x;
    for (int i = tid; i < 864; i += 256) sW[i] = conv_W[i];
    if (tid < 8)  sOW[tid] = out_W[tid];
    if (tid < 2)  sOB[tid] = out_b[tid];
    if (tid < 12) sCB[tid] = conv_b[tid];
    __syncthreads();

    int idx = blockIdx.x * 256 + tid;
    int n  = idx & 511;
    int co = (idx >> 9) % 12;
    int b  = idx / (512*12);

    float y0, y1, y2, y3;
    y0 = y1 = y2 = y3 = sCB[co];
    #pragma unroll
    for (int ci = 0; ci < 8; ci++) {
        #pragma unroll
        for (int kh = 0; kh < 3; kh++) {
            int nn = n + kh - 1;
            float4 v = make_float4(0.f, 0.f, 0.f, 0.f);
            if (nn >= 0 && nn < 512)
                v = *(const float4*)&d_g[(((size_t)b*8 + ci)*512 + nn)*4];
            const float* wr = &sW[(co*8 + ci)*9 + kh*3];
            float w0 = wr[0], w1 = wr[1], w2 = wr[2];
            y0 += v.x*w1 + v.y*w2;
            y1 += v.x*w0 + v.y*w1 + v.z*w2;
            y2 += v.y*w0 + v.z*w1 + v.w*w2;
            y3 += v.z*w0 + v.w*w1;
        }
    }
    float o0 = sOB[0] + y0*sOW[0] + y1*sOW[1] + y2*sOW[2] + y3*sOW[3];
    float o1 = sOB[1] + y0*sOW[4] + y1*sOW[5] + y2*sOW[6] + y3*sOW[7];
    *(float2*)&out[(size_t)idx*2] = make_float2(o0, o1);
}

// ================================ launch =========================================
extern "C" void kernel_launch(void* const* d_in, const int* in_sizes, int n_in,
                              void* d_out, int out_size)
{
    const float* x        = (const float*)d_in[0];
    const float* adj      = (const float*)d_in[1];
    const float* gat_W    = (const float*)d_in[2];
    const float* att_src  = (const float*)d_in[3];
    const float* att_dst  = (const float*)d_in[4];
    const float* gat_bias = (const float*)d_in[5];
    const float* W_ih     = (const float*)d_in[6];
    const float* W_hh     = (const float*)d_in[7];
    const float* b_ih     = (const float*)d_in[8];
    const float* b_hh     = (const float*)d_in[9];
    const float* conv_W   = (const float*)d_in[10];
    const float* conv_b   = (const float*)d_in[11];
    const float* out_W    = (const float*)d_in[12];
    const float* out_b    = (const float*)d_in[13];
    float* out = (float*)d_out;

    cudaFuncSetAttribute(k_attn, cudaFuncAttributeMaxDynamicSharedMemorySize, SME_TOTAL);

    k_proj<<<BTN, 256>>>(x, gat_W, att_src, att_dst);

    dim3 gm(16, 16, BTN), bm(32, 8);
    k_mask<<<gm, bm>>>(adj);

    k_attn<<<BTN*4, 256, SME_TOTAL>>>(gat_bias, W_ih, b_ih);

    k_gru<<<(BB*NN)/256, 256>>>(W_hh, b_hh);

    k_conv<<<768, 256>>>(conv_W, conv_b, out_W, out_b, out);
}

// round 4
// speedup vs baseline: 3.1545x; 1.6392x over previous
#include <cuda_runtime.h>
#include <cuda_fp16.h>
#include <math.h>
#include <cstdint>

#define BB 32
#define TT 8
#define NN 512
#define FF 4
#define HH 64
#define ROWS (BB*TT*NN)
#define BTN  (BB*TT)
#define LOG2E 1.4426950408889634f

// ---------------- scratch (static device globals; no allocation) ----------------
__device__ __half d_WxT[(size_t)BTN*HH*NN];   // 16.8 MB [bt][h][j] fp16
__device__ float  d_asrc[ROWS];               // pre-scaled by log2(e)
__device__ float  d_adst[ROWS];               // pre-scaled by log2(e)
__device__ float  d_gates[(size_t)ROWS*12];
__device__ float  d_g[BB*TT*NN*FF];

// ============ K1: WxT fp16 + a_src/a_dst (log2-scaled) ===========================
__global__ void k_proj(const float* __restrict__ x, const float* __restrict__ gat_W,
                       const float* __restrict__ att_src, const float* __restrict__ att_dst)
{
    __shared__ float4 sx4[NN];
    __shared__ float  sW[256];
    __shared__ float  su[4], sv[4];
    int bt = blockIdx.x, tid = threadIdx.x;
    int w = tid >> 5, lane = tid & 31;

    const float4* gx = (const float4*)(x + (size_t)bt*NN*FF);
    sx4[tid] = gx[tid];
    sx4[tid + 256] = gx[tid + 256];
    if (tid < 256) sW[tid] = gat_W[tid];
    __syncthreads();

    if (w == 0) {
        float as0 = __ldg(&att_src[lane]), as1 = __ldg(&att_src[32 + lane]);
        float ad0 = __ldg(&att_dst[lane]), ad1 = __ldg(&att_dst[32 + lane]);
        #pragma unroll
        for (int f = 0; f < 4; f++) {
            float uu = sW[f*64 + lane]*as0 + sW[f*64 + 32 + lane]*as1;
            float vv = sW[f*64 + lane]*ad0 + sW[f*64 + 32 + lane]*ad1;
            #pragma unroll
            for (int o = 16; o > 0; o >>= 1) {
                uu += __shfl_xor_sync(0xffffffffu, uu, o);
                vv += __shfl_xor_sync(0xffffffffu, vv, o);
            }
            if (lane == 0) { su[f] = uu*LOG2E; sv[f] = vv*LOG2E; }
        }
    }
    __syncthreads();

    __half2* wt = (__half2*)(d_WxT + (size_t)bt*HH*NN);
    for (int h = w; h < 64; h += 8) {
        float w0 = sW[h], w1 = sW[64 + h], w2 = sW[128 + h], w3 = sW[192 + h];
        #pragma unroll
        for (int jc = 0; jc < 8; jc++) {
            int j = jc*64 + lane*2;
            float4 a = sx4[j], b = sx4[j + 1];
            float wx0 = a.x*w0 + a.y*w1 + a.z*w2 + a.w*w3;
            float wx1 = b.x*w0 + b.y*w1 + b.z*w2 + b.w*w3;
            wt[(h*NN + j) >> 1] = __floats2half2_rn(wx0, wx1);
        }
    }
    #pragma unroll
    for (int r = 0; r < 2; r++) {
        int j = tid + r*256;
        float4 a = sx4[j];
        d_asrc[bt*NN + j] = a.x*su[0] + a.y*su[1] + a.z*su[2] + a.w*su[3];
        d_adst[bt*NN + j] = a.x*sv[0] + a.y*sv[1] + a.z*sv[2] + a.w*sv[3];
    }
}

// ===== K2: fused mask + softmax(fp16x2 ex2) + HMMA GEMM + gates, occ=2 ==========
#define SP     0          /* P tile: 128 x 512B (fp16, XOR-swizzled); D reuses */
#define SB     65536      /* B half tile: 64 x 512B */
#define SMASK  98304      /* 128 x 16 uint32 = 8192 */
#define SASRC  106496     /* 512 half = 1024 */
#define SWIH   107520     /* 768 f32 = 3072 */
#define SBIAS  110592     /* 64 f32 */
#define SBIH   110848     /* 16 f32 */
#define SL     110912     /* 128 f32 */
#define SME_TOTAL 111424
#define DSTRIDE 66

__device__ __forceinline__ void mma16816(float* d, const uint32_t* a, const uint32_t* b)
{
    asm volatile("mma.sync.aligned.m16n8k16.row.col.f32.f16.f16.f32 "
        "{%0,%1,%2,%3}, {%4,%5,%6,%7}, {%8,%9}, {%0,%1,%2,%3};"
        : "+f"(d[0]), "+f"(d[1]), "+f"(d[2]), "+f"(d[3])
        : "r"(a[0]), "r"(a[1]), "r"(a[2]), "r"(a[3]), "r"(b[0]), "r"(b[1]));
}

__global__ void __launch_bounds__(256, 2)
k_attn(const float* __restrict__ adj, const float* __restrict__ gat_bias,
       const float* __restrict__ W_ih, const float* __restrict__ b_ih)
{
    extern __shared__ char smem[];
    float* sWih  = (float*)(smem + SWIH);
    float* sBias = (float*)(smem + SBIAS);
    float* sBih  = (float*)(smem + SBIH);
    float* sLf   = (float*)(smem + SL);
    uint32_t* sMask = (uint32_t*)(smem + SMASK);

    int bt    = blockIdx.x >> 2;
    int mtile = blockIdx.x & 3;
    int tid   = threadIdx.x;
    int w     = tid >> 5, lane = tid & 31;

    // ---- small stages ----
    for (int i = tid; i < 768; i += 256) sWih[i] = __ldg(&W_ih[i]);
    if (tid < 64) sBias[tid] = __ldg(&gat_bias[tid]);
    if (tid < 12) sBih[tid]  = __ldg(&b_ih[tid]);
    if (tid < 256) {
        float2 v = *(const float2*)&d_asrc[bt*NN + tid*2];
        ((__half2*)(smem + SASRC))[tid] = __floats2half2_rn(v.x, v.y);
    }

    // ---- mask build: lane accumulates its own i-column bits over 32 j rows ----
    const float* adjbt = adj + (size_t)bt*NN*NN;
    #pragma unroll 1
    for (int t8 = 0; t8 < 8; t8++) {
        int t = w*8 + t8;
        int itile = t >> 4;               // 0..3
        int jt    = t & 15;               // 0..15
        int ig = mtile*128 + itile*32 + lane;
        uint32_t word = 0;
        #pragma unroll
        for (int jl = 0; jl < 32; jl++) {
            float v = __ldg(&adjbt[(size_t)(jt*32 + jl)*NN + ig]);
            word |= (v != 0.0f ? 1u : 0u) << jl;
        }
        if ((ig >> 5) == jt) word |= 1u << (ig & 31);
        sMask[(itile*32 + lane)*16 + jt] = word;
    }
    __syncthreads();

    // ---- warp-uniform max of (log2-scaled) a_src from fp16 values ----
    float sxmax;
    {
        const __half2* sa2 = (const __half2*)(smem + SASRC);
        __half2 mx = __floats2half2_rn(-60000.f, -60000.f);
        #pragma unroll
        for (int k = 0; k < 8; k++) mx = __hmax2(mx, sa2[lane*8 + k]);
        float m = fmaxf(__low2float(mx), __high2float(mx));
        #pragma unroll
        for (int o = 16; o > 0; o >>= 1) m = fmaxf(m, __shfl_xor_sync(0xffffffffu, m, o));
        sxmax = m;
    }

    const __half2 c02 = __floats2half2_rn(0.2f, 0.2f);
    float lpr[16];
    #pragma unroll
    for (int qi = 0; qi < 16; qi++) lpr[qi] = 0.0f;

    float acc[2][4][4];
    #pragma unroll
    for (int mf = 0; mf < 2; mf++)
        #pragma unroll
        for (int nf = 0; nf < 4; nf++)
            #pragma unroll
            for (int r = 0; r < 4; r++) acc[mf][nf][r] = 0.0f;

    int mg = w & 3, ng = w >> 2;
    int mbase = mg*32, nbase = ng*32;
    int tm = lane >> 2;
    int tc4 = (lane & 3)*4;

    #pragma unroll 1
    for (int hv = 0; hv < 2; hv++) {
        // ---- stage B half: WxT[64][hv*256 .. +256) -> swizzled smem ----
        {
            const uint4* gB = (const uint4*)(d_WxT + (size_t)bt*HH*NN);
            #pragma unroll
            for (int t = tid; t < 2048; t += 256) {
                int n = t >> 5, c = t & 31;
                uint4 v = gB[n*64 + hv*32 + c];
                *(uint4*)(smem + SB + n*512 + ((c ^ (n & 7)) << 4)) = v;
            }
        }
        // ---- phase A: P numerators fp16x2 ----
        #pragma unroll 1
        for (int qi = 0; qi < 16; qi++) {
            int q = w*16 + qi;
            float dq = __ldg(&d_adst[bt*NN + mtile*128 + q]);
            float mqf = fmaxf(0.0f, dq + sxmax);
            __half2 dq2 = __float2half2_rn(dq);
            __half2 mq2 = __float2half2_rn(mqf);
            float lsum = 0.0f;
            #pragma unroll
            for (int jt = 0; jt < 4; jt++) {
                __half2 sj2 = ((const __half2*)(smem + SASRC))[hv*128 + jt*32 + lane];
                __half2 t2 = __hadd2(dq2, sj2);
                __half2 l2 = __hmax2(t2, __hmul2(t2, c02));
                __half2 e2 = __hsub2(l2, mq2);
                uint32_t p;
                asm("ex2.approx.f16x2 %0, %1;" : "=r"(p) : "r"(*(uint32_t*)&e2));
                uint32_t wrd = sMask[q*16 + hv*8 + jt*2 + (lane >> 4)];
                int bit = (lane & 15)*2;
                uint32_t m32 = (((wrd >> bit) & 1u) ? 0x0000FFFFu : 0u)
                             | (((wrd >> bit) & 2u) ? 0xFFFF0000u : 0u);
                p &= m32;
                int kb = jt*128 + lane*4;
                *(uint32_t*)(smem + SP + q*512 + (kb ^ ((q & 7) << 4))) = p;
                __half2 hp = *(__half2*)&p;
                float2 pf = __half22float2(hp);
                lsum += pf.x + pf.y;
            }
            lpr[qi] += lsum;
        }
        __syncthreads();

        // ---- GEMM half: 16 k-steps of 16 ----
        const char* Pb = smem + SP;
        const char* Bb = smem + SB;
        #pragma unroll 2
        for (int ks = 0; ks < 16; ks++) {
            int kb = ks*32 + tc4;
            uint32_t a[2][4], b[4][2];
            #pragma unroll
            for (int mf = 0; mf < 2; mf++) {
                int r0 = mbase + mf*16 + tm, r1 = r0 + 8;
                uint32_t sw0 = (uint32_t)((r0 & 7) << 4);
                uint32_t sw1 = (uint32_t)((r1 & 7) << 4);
                a[mf][0] = *(const uint32_t*)(Pb + r0*512 + (kb ^ sw0));
                a[mf][1] = *(const uint32_t*)(Pb + r1*512 + (kb ^ sw1));
                a[mf][2] = *(const uint32_t*)(Pb + r0*512 + ((kb + 16) ^ sw0));
                a[mf][3] = *(const uint32_t*)(Pb + r1*512 + ((kb + 16) ^ sw1));
            }
            #pragma unroll
            for (int nf = 0; nf < 4; nf++) {
                int n = nbase + nf*8 + tm;
                uint32_t sw = (uint32_t)((n & 7) << 4);
                b[nf][0] = *(const uint32_t*)(Bb + n*512 + (kb ^ sw));
                b[nf][1] = *(const uint32_t*)(Bb + n*512 + ((kb + 16) ^ sw));
            }
            #pragma unroll
            for (int mf = 0; mf < 2; mf++)
                #pragma unroll
                for (int nf = 0; nf < 4; nf++)
                    mma16816(acc[mf][nf], a[mf], b[nf]);
        }
        __syncthreads();   // P/B consumed; safe to restage next half
    }

    // ---- row sums -> sL ----
    #pragma unroll
    for (int qi = 0; qi < 16; qi++) {
        float l = lpr[qi];
        #pragma unroll
        for (int o = 16; o > 0; o >>= 1) l += __shfl_xor_sync(0xffffffffu, l, o);
        if (lane == 0) sLf[w*16 + qi] = l;
    }
    __syncthreads();

    // ---- normalize + bias -> D (reuses P region) ----
    float* D = (float*)(smem + SP);
    #pragma unroll
    for (int mf = 0; mf < 2; mf++) {
        int r = mbase + mf*16 + tm;
        float inv0 = 1.0f / sLf[r];
        float inv8 = 1.0f / sLf[r + 8];
        #pragma unroll
        for (int nf = 0; nf < 4; nf++) {
            int n = nbase + nf*8 + (lane & 3)*2;
            float b0 = sBias[n], b1 = sBias[n + 1];
            *(float2*)&D[r*DSTRIDE + n]       = make_float2(acc[mf][nf][0]*inv0 + b0,
                                                            acc[mf][nf][1]*inv0 + b1);
            *(float2*)&D[(r + 8)*DSTRIDE + n] = make_float2(acc[mf][nf][2]*inv8 + b0,
                                                            acc[mf][nf][3]*inv8 + b1);
        }
    }
    __syncthreads();

    // ---- fused 64->12 GRU input-gate projection ----
    if (tid < 128) {
        int q = tid;
        float g[12];
        #pragma unroll
        for (int k = 0; k < 12; k++) g[k] = sBih[k];
        #pragma unroll 8
        for (int h = 0; h < 64; h++) {
            float ov = D[q*DSTRIDE + h];
            #pragma unroll
            for (int k = 0; k < 12; k++) g[k] = fmaf(sWih[k*64 + h], ov, g[k]);
        }
        float* gp = d_gates + ((size_t)bt*NN + mtile*128 + q)*12;
        *(float4*)(gp + 0) = make_float4(g[0], g[1], g[2],  g[3]);
        *(float4*)(gp + 4) = make_float4(g[4], g[5], g[6],  g[7]);
        *(float4*)(gp + 8) = make_float4(g[8], g[9], g[10], g[11]);
    }
}

// ===================== K3: GRU recurrence ========================================
__device__ __forceinline__ float sigm(float v) { return 1.0f / (1.0f + __expf(-v)); }

__global__ void k_gru(const float* __restrict__ W_hh, const float* __restrict__ b_hh)
{
    __shared__ float sWhh[48], sbhh[12];
    int tid = threadIdx.x;
    if (tid < 48) sWhh[tid] = W_hh[tid];
    if (tid < 12) sbhh[tid] = b_hh[tid];
    __syncthreads();
    int q = blockIdx.x * blockDim.x + tid;
    if (q >= BB*NN) return;
    int b = q >> 9, n = q & 511;
    float h0 = 0.f, h1 = 0.f, h2 = 0.f, h3 = 0.f;
    #pragma unroll
    for (int s = 0; s < TT; s++) {
        const float* gx = d_gates + (size_t)(q*8 + s)*12;
        float4 g0 = *(const float4*)(gx + 0);
        float4 g1 = *(const float4*)(gx + 4);
        float4 g2 = *(const float4*)(gx + 8);
        float gh[12];
        #pragma unroll
        for (int k = 0; k < 12; k++)
            gh[k] = sbhh[k] + sWhh[k*4+0]*h0 + sWhh[k*4+1]*h1
                            + sWhh[k*4+2]*h2 + sWhh[k*4+3]*h3;
        float r0 = sigm(g0.x + gh[0]), r1 = sigm(g0.y + gh[1]);
        float r2 = sigm(g0.z + gh[2]), r3 = sigm(g0.w + gh[3]);
        float z0 = sigm(g1.x + gh[4]), z1 = sigm(g1.y + gh[5]);
        float z2 = sigm(g1.z + gh[6]), z3 = sigm(g1.w + gh[7]);
        float c0 = tanhf(g2.x + r0*gh[8]),  c1 = tanhf(g2.y + r1*gh[9]);
        float c2 = tanhf(g2.z + r2*gh[10]), c3 = tanhf(g2.w + r3*gh[11]);
        h0 = (1.0f - z0)*c0 + z0*h0;
        h1 = (1.0f - z1)*c1 + z1*h1;
        h2 = (1.0f - z2)*c2 + z2*h2;
        h3 = (1.0f - z3)*c3 + z3*h3;
        *(float4*)&d_g[(((size_t)b*TT + s)*NN + n)*4] = make_float4(h0, h1, h2, h3);
    }
}

// ============== K4: Conv2d(8->12, 3x3, SAME) + Linear(4->2) ======================
__global__ void k_conv(const float* __restrict__ conv_W, const float* __restrict__ conv_b,
                       const float* __restrict__ out_W,  const float* __restrict__ out_b,
                       float* __restrict__ out)
{
    __shared__ float sW[864];
    __shared__ float sOW[8], sOB[2], sCB[12];
    int tid = threadIdx.x;
    for (int i = tid; i < 864; i += 256) sW[i] = conv_W[i];
    if (tid < 8)  sOW[tid] = out_W[tid];
    if (tid < 2)  sOB[tid] = out_b[tid];
    if (tid < 12) sCB[tid] = conv_b[tid];
    __syncthreads();

    int idx = blockIdx.x * 256 + tid;
    int n  = idx & 511;
    int co = (idx >> 9) % 12;
    int b  = idx / (512*12);

    float y0, y1, y2, y3;
    y0 = y1 = y2 = y3 = sCB[co];
    #pragma unroll
    for (int ci = 0; ci < 8; ci++) {
        #pragma unroll
        for (int kh = 0; kh < 3; kh++) {
            int nn = n + kh - 1;
            float4 v = make_float4(0.f, 0.f, 0.f, 0.f);
            if (nn >= 0 && nn < 512)
                v = *(const float4*)&d_g[(((size_t)b*8 + ci)*512 + nn)*4];
            const float* wr = &sW[(co*8 + ci)*9 + kh*3];
            float w0 = wr[0], w1 = wr[1], w2 = wr[2];
            y0 += v.x*w1 + v.y*w2;
            y1 += v.x*w0 + v.y*w1 + v.z*w2;
            y2 += v.y*w0 + v.z*w1 + v.w*w2;
            y3 += v.z*w0 + v.w*w1;
        }
    }
    float o0 = sOB[0] + y0*sOW[0] + y1*sOW[1] + y2*sOW[2] + y3*sOW[3];
    float o1 = sOB[1] + y0*sOW[4] + y1*sOW[5] + y2*sOW[6] + y3*sOW[7];
    *(float2*)&out[(size_t)idx*2] = make_float2(o0, o1);
}

// ================================ launch =========================================
extern "C" void kernel_launch(void* const* d_in, const int* in_sizes, int n_in,
                              void* d_out, int out_size)
{
    const float* x        = (const float*)d_in[0];
    const float* adj      = (const float*)d_in[1];
    const float* gat_W    = (const float*)d_in[2];
    const float* att_src  = (const float*)d_in[3];
    const float* att_dst  = (const float*)d_in[4];
    const float* gat_bias = (const float*)d_in[5];
    const float* W_ih     = (const float*)d_in[6];
    const float* W_hh     = (const float*)d_in[7];
    const float* b_ih     = (const float*)d_in[8];
    const float* b_hh     = (const float*)d_in[9];
    const float* conv_W   = (const float*)d_in[10];
    const float* conv_b   = (const float*)d_in[11];
    const float* out_W    = (const float*)d_in[12];
    const float* out_b    = (const float*)d_in[13];
    float* out = (float*)d_out;

    cudaFuncSetAttribute(k_attn, cudaFuncAttributeMaxDynamicSharedMemorySize, SME_TOTAL);

    k_proj<<<BTN, 256>>>(x, gat_W, att_src, att_dst);
    k_attn<<<BTN*4, 256, SME_TOTAL>>>(adj, gat_bias, W_ih, b_ih);
    k_gru<<<(BB*NN)/128, 128>>>(W_hh, b_hh);
    k_conv<<<768, 256>>>(conv_W, conv_b, out_W, out_b, out);
}